// round 1
// baseline (speedup 1.0000x reference)
#include <cuda_runtime.h>
#include <cstddef>

#define D 64
#define NH 4
#define DH 16
#define FF 2048
#define VV 1000000
#define STEPS 10
#define EPS 1e-5f

// Persistent inter-kernel state (static device globals: no allocation).
__device__ float g_x1[STEPS * D];            // post-LN1 activations (current layer)
__device__ float g_y[STEPS * D];             // FFN output (pre-residual)
__device__ float g_h[STEPS * FF];            // FFN hidden
__device__ unsigned long long g_amax[STEPS]; // packed argmax accumulators
__device__ int g_gen[STEPS];                 // decoded generated indices

__device__ __forceinline__ unsigned int fkey(float f) {
    unsigned int u = __float_as_uint(f);
    return (u & 0x80000000u) ? ~u : (u | 0x80000000u);
}
__device__ __forceinline__ int dec_idx(unsigned long long k) {
    return (int)(0xFFFFFFFFu - (unsigned int)(k & 0xFFFFFFFFull));
}

// ---------------------------------------------------------------------------
// Attention kernel: 1 block. layer 0 builds the input stack (ht + generated
// embeddings + pos); layer 1 applies LN2 of layer 0 first. Ends with
// residual + LN1 written to g_x1.
// ---------------------------------------------------------------------------
__global__ void attn_kernel(const float* __restrict__ ht,
                            const float* __restrict__ emb,
                            const float* __restrict__ pos,
                            const float* __restrict__ ipw,
                            const float* __restrict__ ipb,
                            const float* __restrict__ ow,
                            const float* __restrict__ ob,
                            const float* __restrict__ ln1w,
                            const float* __restrict__ ln1b,
                            const float* __restrict__ ln2w,
                            const float* __restrict__ ln2b,
                            int layer, int S, int t) {
    __shared__ float x[STEPS * D];
    __shared__ float qkv[STEPS * 3 * D];
    __shared__ float sc[NH * STEPS * STEPS];
    __shared__ float o[STEPS * D];
    __shared__ float stat[STEPS * 2];
    int tid = threadIdx.x;
    int nt = blockDim.x;

    if (layer == 0) {
        if (tid == 0) {
            if (t > 0) g_gen[t - 1] = dec_idx(g_amax[t - 1]);
            g_amax[t] = 0ull; // reset accumulator for this step (every replay)
        }
        __syncthreads();
        for (int i = tid; i < S * D; i += nt) {
            int s = i >> 6, d = i & 63;
            float base = (s == 0) ? ht[d] : emb[(size_t)g_gen[s - 1] * D + d];
            x[i] = base + pos[i];
        }
    } else {
        // x = LN(g_x1 + g_y) with layer-0 ln2 params
        for (int i = tid; i < S * D; i += nt) x[i] = g_x1[i] + g_y[i];
        __syncthreads();
        if (tid < S) {
            float m = 0.f;
            for (int d = 0; d < D; d++) m += x[tid * D + d];
            m *= (1.f / D);
            float vv = 0.f;
            for (int d = 0; d < D; d++) { float df = x[tid * D + d] - m; vv += df * df; }
            vv *= (1.f / D);
            stat[tid * 2] = m;
            stat[tid * 2 + 1] = rsqrtf(vv + EPS);
        }
        __syncthreads();
        for (int i = tid; i < S * D; i += nt) {
            int s = i >> 6, d = i & 63;
            x[i] = (x[i] - stat[s * 2]) * stat[s * 2 + 1] * ln2w[d] + ln2b[d];
        }
    }
    __syncthreads();

    // qkv = x @ ipw[layer]^T + ipb[layer]
    const float* W = ipw + (size_t)layer * 3 * D * D;
    const float* B = ipb + layer * 3 * D;
    for (int i = tid; i < S * 3 * D; i += nt) {
        int s = i / (3 * D), j = i % (3 * D);
        const float* wr = W + (size_t)j * D;
        const float* xr = x + s * D;
        float acc = B[j];
#pragma unroll
        for (int d = 0; d < D; d++) acc += xr[d] * wr[d];
        qkv[i] = acc;
    }
    __syncthreads();

    // scores[h][r][c] = q[r,h,:].k[c,h,:] / 4
    for (int i = tid; i < NH * S * S; i += nt) {
        int h = i / (S * S), r = (i / S) % S, c = i % S;
        const float* q = qkv + r * 3 * D + h * DH;
        const float* k = qkv + c * 3 * D + D + h * DH;
        float acc = 0.f;
#pragma unroll
        for (int d = 0; d < DH; d++) acc += q[d] * k[d];
        sc[(h * S + r) * S + c] = acc * 0.25f;
    }
    __syncthreads();

    // softmax rows
    for (int i = tid; i < NH * S; i += nt) {
        float* row = sc + i * S;
        float mx = row[0];
        for (int c = 1; c < S; c++) mx = fmaxf(mx, row[c]);
        float sm = 0.f;
        for (int c = 0; c < S; c++) { float e = expf(row[c] - mx); row[c] = e; sm += e; }
        float inv = 1.f / sm;
        for (int c = 0; c < S; c++) row[c] *= inv;
    }
    __syncthreads();

    // o[s, h*16+d] = sum_c attn[h,s,c] * v[c,h,d]
    for (int i = tid; i < S * D; i += nt) {
        int s = i >> 6, col = i & 63;
        int h = col >> 4, d = col & 15;
        const float* a = sc + (h * S + s) * S;
        float acc = 0.f;
        for (int c = 0; c < S; c++) acc += a[c] * qkv[c * 3 * D + 2 * D + h * DH + d];
        o[i] = acc;
    }
    __syncthreads();

    // out proj + residual (reuse qkv buffer)
    const float* OW = ow + (size_t)layer * D * D;
    const float* OB = ob + layer * D;
    for (int i = tid; i < S * D; i += nt) {
        int s = i >> 6, e = i & 63;
        const float* wr = OW + (size_t)e * D;
        const float* orow = o + s * D;
        float acc = OB[e];
#pragma unroll
        for (int k2 = 0; k2 < D; k2++) acc += orow[k2] * wr[k2];
        qkv[i] = x[i] + acc;
    }
    __syncthreads();
    if (tid < S) {
        float m = 0.f;
        for (int d = 0; d < D; d++) m += qkv[tid * D + d];
        m *= (1.f / D);
        float vv = 0.f;
        for (int d = 0; d < D; d++) { float df = qkv[tid * D + d] - m; vv += df * df; }
        vv *= (1.f / D);
        stat[tid * 2] = m;
        stat[tid * 2 + 1] = rsqrtf(vv + EPS);
    }
    __syncthreads();
    const float* L1W = ln1w + layer * D;
    const float* L1B = ln1b + layer * D;
    for (int i = tid; i < S * D; i += nt) {
        int s = i >> 6, d = i & 63;
        g_x1[i] = (qkv[i] - stat[s * 2]) * stat[s * 2 + 1] * L1W[d] + L1B[d];
    }
}

// ---------------------------------------------------------------------------
// FFN1: h = relu(x1 @ f1w^T + f1b). One thread per FF unit, S templated so
// accumulators stay in registers.
// ---------------------------------------------------------------------------
template <int S>
__global__ void ffn1_kernel(const float* __restrict__ f1w,
                            const float* __restrict__ f1b, int layer) {
    __shared__ float xs[S * D];
    int tid = threadIdx.x;
    for (int i = tid; i < S * D; i += 256) xs[i] = g_x1[i];
    __syncthreads();
    int f = blockIdx.x * 256 + tid;
    const float4* wr = (const float4*)(f1w + (size_t)layer * FF * D + (size_t)f * D);
    float b = f1b[layer * FF + f];
    float acc[S];
#pragma unroll
    for (int s = 0; s < S; s++) acc[s] = b;
#pragma unroll
    for (int k = 0; k < 16; k++) {
        float4 w4 = wr[k];
#pragma unroll
        for (int s = 0; s < S; s++) {
            const float* xr = xs + s * D + k * 4;
            acc[s] += w4.x * xr[0] + w4.y * xr[1] + w4.z * xr[2] + w4.w * xr[3];
        }
    }
#pragma unroll
    for (int s = 0; s < S; s++) g_h[s * FF + f] = fmaxf(acc[s], 0.f);
}

// ---------------------------------------------------------------------------
// FFN2: y = h @ f2w^T + f2b. One block per output dim d (64 blocks),
// coalesced reads of the f2w row and g_h.
// ---------------------------------------------------------------------------
template <int S>
__global__ void ffn2_kernel(const float* __restrict__ f2w,
                            const float* __restrict__ f2b, int layer) {
    int tid = threadIdx.x, d = blockIdx.x;
    const float* wr = f2w + (size_t)layer * D * FF + (size_t)d * FF;
    float acc[S];
#pragma unroll
    for (int s = 0; s < S; s++) acc[s] = 0.f;
    for (int f = tid; f < FF; f += 256) {
        float w = wr[f];
#pragma unroll
        for (int s = 0; s < S; s++) acc[s] += g_h[s * FF + f] * w;
    }
    __shared__ float ws[8][S];
    int lane = tid & 31, wid = tid >> 5;
#pragma unroll
    for (int s = 0; s < S; s++) {
        float v = acc[s];
#pragma unroll
        for (int m = 16; m; m >>= 1) v += __shfl_xor_sync(0xffffffffu, v, m);
        if (lane == 0) ws[wid][s] = v;
    }
    __syncthreads();
    if (tid < S) {
        float sum = 0.f;
#pragma unroll
        for (int w = 0; w < 8; w++) sum += ws[w][tid];
        g_y[tid * D + d] = sum + f2b[layer * D + d];
    }
}

// ---------------------------------------------------------------------------
// Logits + argmax: prologue computes x_last = LN2(x1+y) per block (cheap,
// redundant), then HBM-bound scan of item_emb. 8-lane groups per row,
// 2x float4 per lane, fully-coalesced 128B transactions.
// ---------------------------------------------------------------------------
__global__ void logits_kernel(const float* __restrict__ emb,
                              const float* __restrict__ ln2w,
                              const float* __restrict__ ln2b,
                              float* __restrict__ out, int t, int S) {
    __shared__ float xr[D];
    __shared__ float4 xs4[D / 4];
    __shared__ float stat2[2];
    int tid = threadIdx.x;
    if (tid < D) xr[tid] = g_x1[(S - 1) * D + tid] + g_y[(S - 1) * D + tid];
    __syncthreads();
    if (tid == 0) {
        float m = 0.f;
        for (int d = 0; d < D; d++) m += xr[d];
        m *= (1.f / D);
        float vv = 0.f;
        for (int d = 0; d < D; d++) { float df = xr[d] - m; vv += df * df; }
        vv *= (1.f / D);
        stat2[0] = m;
        stat2[1] = rsqrtf(vv + EPS);
    }
    __syncthreads();
    if (tid < D) {
        // layer-1 LN2 params
        float val = (xr[tid] - stat2[0]) * stat2[1] * ln2w[D + tid] + ln2b[D + tid];
        ((float*)xs4)[tid] = val;
    }
    __syncthreads();

    int lane = tid & 31, wid = tid >> 5;
    int grp = lane >> 3, l8 = lane & 7;
    unsigned long long best = 0ull;
    float* orow = out + (size_t)t * VV;
    float4 xa = xs4[l8], xb = xs4[8 + l8];
    for (int base = blockIdx.x * 32; base < VV; base += gridDim.x * 32) {
        int v = base + wid * 4 + grp;
        const float4* p = (const float4*)(emb + (size_t)v * D);
        float4 a = p[l8];
        float4 b2 = p[8 + l8];
        float dot = a.x * xa.x + a.y * xa.y + a.z * xa.z + a.w * xa.w
                  + b2.x * xb.x + b2.y * xb.y + b2.z * xb.z + b2.w * xb.w;
        dot += __shfl_xor_sync(0xffffffffu, dot, 1);
        dot += __shfl_xor_sync(0xffffffffu, dot, 2);
        dot += __shfl_xor_sync(0xffffffffu, dot, 4);
        if (l8 == 0) {
            orow[v] = dot;
            unsigned long long key =
                ((unsigned long long)fkey(dot) << 32) | (0xFFFFFFFFu - (unsigned)v);
            if (key > best) best = key;
        }
    }
    __shared__ unsigned long long bs[256];
    bs[tid] = best;
    __syncthreads();
    for (int o2 = 128; o2; o2 >>= 1) {
        if (tid < o2) { if (bs[tid + o2] > bs[tid]) bs[tid] = bs[tid + o2]; }
        __syncthreads();
    }
    if (tid == 0) atomicMax(&g_amax[t], bs[0]);
}

__global__ void fin_kernel(float* out, int out_size) {
    if (threadIdx.x == 0) g_gen[STEPS - 1] = dec_idx(g_amax[STEPS - 1]);
    __syncthreads();
    if (out_size >= STEPS * VV + STEPS && threadIdx.x < STEPS)
        out[(size_t)STEPS * VV + threadIdx.x] = (float)g_gen[threadIdx.x];
}

// ---------------------------------------------------------------------------
static void run_ffn1(const float* w, const float* b, int layer, int S) {
    switch (S) {
        case 1: ffn1_kernel<1><<<8, 256>>>(w, b, layer); break;
        case 2: ffn1_kernel<2><<<8, 256>>>(w, b, layer); break;
        case 3: ffn1_kernel<3><<<8, 256>>>(w, b, layer); break;
        case 4: ffn1_kernel<4><<<8, 256>>>(w, b, layer); break;
        case 5: ffn1_kernel<5><<<8, 256>>>(w, b, layer); break;
        case 6: ffn1_kernel<6><<<8, 256>>>(w, b, layer); break;
        case 7: ffn1_kernel<7><<<8, 256>>>(w, b, layer); break;
        case 8: ffn1_kernel<8><<<8, 256>>>(w, b, layer); break;
        case 9: ffn1_kernel<9><<<8, 256>>>(w, b, layer); break;
        case 10: ffn1_kernel<10><<<8, 256>>>(w, b, layer); break;
    }
}
static void run_ffn2(const float* w, const float* b, int layer, int S) {
    switch (S) {
        case 1: ffn2_kernel<1><<<64, 256>>>(w, b, layer); break;
        case 2: ffn2_kernel<2><<<64, 256>>>(w, b, layer); break;
        case 3: ffn2_kernel<3><<<64, 256>>>(w, b, layer); break;
        case 4: ffn2_kernel<4><<<64, 256>>>(w, b, layer); break;
        case 5: ffn2_kernel<5><<<64, 256>>>(w, b, layer); break;
        case 6: ffn2_kernel<6><<<64, 256>>>(w, b, layer); break;
        case 7: ffn2_kernel<7><<<64, 256>>>(w, b, layer); break;
        case 8: ffn2_kernel<8><<<64, 256>>>(w, b, layer); break;
        case 9: ffn2_kernel<9><<<64, 256>>>(w, b, layer); break;
        case 10: ffn2_kernel<10><<<64, 256>>>(w, b, layer); break;
    }
}

extern "C" void kernel_launch(void* const* d_in, const int* in_sizes, int n_in,
                              void* d_out, int out_size) {
    const float* ht  = (const float*)d_in[0];
    const float* emb = (const float*)d_in[1];
    const float* pos = (const float*)d_in[2];
    const float* ipw = (const float*)d_in[3];
    const float* ipb = (const float*)d_in[4];
    const float* ow  = (const float*)d_in[5];
    const float* ob  = (const float*)d_in[6];
    const float* l1w = (const float*)d_in[7];
    const float* l1b = (const float*)d_in[8];
    const float* l2w = (const float*)d_in[9];
    const float* l2b = (const float*)d_in[10];
    const float* f1w = (const float*)d_in[11];
    const float* f1b = (const float*)d_in[12];
    const float* f2w = (const float*)d_in[13];
    const float* f2b = (const float*)d_in[14];
    float* out = (float*)d_out;

    for (int t = 0; t < STEPS; t++) {
        int S = t + 1;
        attn_kernel<<<1, 512>>>(ht, emb, pos, ipw, ipb, ow, ob,
                                l1w, l1b, l2w, l2b, 0, S, t);
        run_ffn1(f1w, f1b, 0, S);
        run_ffn2(f2w, f2b, 0, S);
        attn_kernel<<<1, 512>>>(ht, emb, pos, ipw, ipb, ow, ob,
                                l1w, l1b, l2w, l2b, 1, S, t);
        run_ffn1(f1w, f1b, 1, S);
        run_ffn2(f2w, f2b, 1, S);
        logits_kernel<<<1184, 256>>>(emb, l2w, l2b, out, t, S);
    }
    fin_kernel<<<1, 32>>>(out, out_size);
}

// round 2
// speedup vs baseline: 2.2506x; 2.2506x over previous
#include <cuda_runtime.h>
#include <cuda_fp16.h>
#include <cstddef>

#define D 64
#define NH 4
#define DH 16
#define FF 2048
#define VV 1000000
#define STEPS 10
#define EPS 1e-5f

// Persistent inter-kernel state (static device globals: no allocation).
__device__ float g_x1[STEPS * D];            // post-LN1 activations
__device__ float g_y[STEPS * D];             // FFN output (bias-seeded, atomically accumulated)
__device__ unsigned long long g_amax[STEPS]; // packed argmax accumulators
__device__ int g_gen[STEPS];                 // decoded generated indices
__device__ uint4 g_embh4[VV * D / 8];        // 128MB fp16 copy of item_emb (written by step-0 logits)

__device__ __forceinline__ unsigned int fkey(float f) {
    unsigned int u = __float_as_uint(f);
    return (u & 0x80000000u) ? ~u : (u | 0x80000000u);
}
__device__ __forceinline__ int dec_idx(unsigned long long k) {
    return (int)(0xFFFFFFFFu - (unsigned int)(k & 0xFFFFFFFFull));
}
__device__ __forceinline__ float dot4(float4 a, float4 b) {
    return a.x * b.x + a.y * b.y + a.z * b.z + a.w * b.w;
}
__device__ __forceinline__ uint4 pack8(float4 a, float4 b) {
    uint4 o;
    __half2 h;
    h = __floats2half2_rn(a.x, a.y); o.x = *(unsigned int*)&h;
    h = __floats2half2_rn(a.z, a.w); o.y = *(unsigned int*)&h;
    h = __floats2half2_rn(b.x, b.y); o.z = *(unsigned int*)&h;
    h = __floats2half2_rn(b.z, b.w); o.w = *(unsigned int*)&h;
    return o;
}
__device__ __forceinline__ float dot8h(uint4 q, float4 xa, float4 xb) {
    __half2* hp = (__half2*)&q;
    float2 f0 = __half22float2(hp[0]), f1 = __half22float2(hp[1]);
    float2 f2 = __half22float2(hp[2]), f3 = __half22float2(hp[3]);
    return f0.x * xa.x + f0.y * xa.y + f1.x * xa.z + f1.y * xa.w
         + f2.x * xb.x + f2.y * xb.y + f3.x * xb.z + f3.y * xb.w;
}

// ---------------------------------------------------------------------------
// Attention kernel: 1 block, 512 threads. Layer 0 builds the input stack;
// layer 1 applies the previous layer's residual+LN2 first. Ends with
// residual+LN1 to g_x1, and seeds g_y with the upcoming FFN's bias.
// ---------------------------------------------------------------------------
__global__ void attn_kernel(const float* __restrict__ ht,
                            const float* __restrict__ emb,
                            const float* __restrict__ pos,
                            const float* __restrict__ ipw,
                            const float* __restrict__ ipb,
                            const float* __restrict__ ow,
                            const float* __restrict__ ob,
                            const float* __restrict__ ln1w,
                            const float* __restrict__ ln1b,
                            const float* __restrict__ ln2w,
                            const float* __restrict__ ln2b,
                            const float* __restrict__ f2b,
                            int layer, int S, int t) {
    __shared__ __align__(16) float x[STEPS * D];
    __shared__ __align__(16) float qkv[STEPS * 3 * D];
    __shared__ __align__(16) float o[STEPS * D];
    __shared__ float sc[NH * STEPS * STEPS];
    __shared__ float stat[STEPS * 2];
    int tid = threadIdx.x;
    int nt = blockDim.x;

    if (layer == 0) {
        if (tid == 0) {
            if (t > 0) g_gen[t - 1] = dec_idx(g_amax[t - 1]);
            g_amax[t] = 0ull;
        }
        __syncthreads();
        for (int i = tid; i < S * D; i += nt) {
            int s = i >> 6, d = i & 63;
            float base = (s == 0) ? ht[d] : emb[(size_t)g_gen[s - 1] * D + d];
            x[i] = base + pos[i];
        }
    } else {
        for (int i = tid; i < S * D; i += nt) x[i] = g_x1[i] + g_y[i];
        __syncthreads();
        if (tid < S) {
            float m = 0.f;
            for (int d = 0; d < D; d++) m += x[tid * D + d];
            m *= (1.f / D);
            float vv = 0.f;
            for (int d = 0; d < D; d++) { float df = x[tid * D + d] - m; vv += df * df; }
            vv *= (1.f / D);
            stat[tid * 2] = m;
            stat[tid * 2 + 1] = rsqrtf(vv + EPS);
        }
        __syncthreads();
        for (int i = tid; i < S * D; i += nt) {
            int s = i >> 6, d = i & 63;
            x[i] = (x[i] - stat[s * 2]) * stat[s * 2 + 1] * ln2w[d] + ln2b[d];
        }
    }
    __syncthreads();

    // qkv = x @ ipw[layer]^T + ipb[layer]  (float4-vectorized weight rows)
    const float* W = ipw + (size_t)layer * 3 * D * D;
    const float* B = ipb + layer * 3 * D;
    for (int i = tid; i < S * 3 * D; i += nt) {
        int s = i / (3 * D), j = i % (3 * D);
        const float4* wr = (const float4*)(W + (size_t)j * D);
        const float4* xr = (const float4*)(x + s * D);
        float acc = B[j];
#pragma unroll
        for (int k = 0; k < 16; k++) acc += dot4(wr[k], xr[k]);
        qkv[i] = acc;
    }
    __syncthreads();

    // scores
    for (int i = tid; i < NH * S * S; i += nt) {
        int h = i / (S * S), r = (i / S) % S, c = i % S;
        const float* q = qkv + r * 3 * D + h * DH;
        const float* k = qkv + c * 3 * D + D + h * DH;
        float acc = 0.f;
#pragma unroll
        for (int d = 0; d < DH; d++) acc += q[d] * k[d];
        sc[(h * S + r) * S + c] = acc * 0.25f;
    }
    __syncthreads();

    // softmax rows
    for (int i = tid; i < NH * S; i += nt) {
        float* row = sc + i * S;
        float mx = row[0];
        for (int c = 1; c < S; c++) mx = fmaxf(mx, row[c]);
        float sm = 0.f;
        for (int c = 0; c < S; c++) { float e = expf(row[c] - mx); row[c] = e; sm += e; }
        float inv = 1.f / sm;
        for (int c = 0; c < S; c++) row[c] *= inv;
    }
    __syncthreads();

    // o = attn @ v
    for (int i = tid; i < S * D; i += nt) {
        int s = i >> 6, col = i & 63;
        int h = col >> 4, d = col & 15;
        const float* a = sc + (h * S + s) * S;
        float acc = 0.f;
        for (int c = 0; c < S; c++) acc += a[c] * qkv[c * 3 * D + 2 * D + h * DH + d];
        o[i] = acc;
    }
    __syncthreads();

    // out proj + residual (reuse qkv)
    const float* OW = ow + (size_t)layer * D * D;
    const float* OB = ob + layer * D;
    for (int i = tid; i < S * D; i += nt) {
        int s = i >> 6, e = i & 63;
        const float4* wr = (const float4*)(OW + (size_t)e * D);
        const float4* orow = (const float4*)(o + s * D);
        float acc = OB[e];
#pragma unroll
        for (int k2 = 0; k2 < 16; k2++) acc += dot4(wr[k2], orow[k2]);
        qkv[i] = x[i] + acc;
    }
    __syncthreads();
    if (tid < S) {
        float m = 0.f;
        for (int d = 0; d < D; d++) m += qkv[tid * D + d];
        m *= (1.f / D);
        float vv = 0.f;
        for (int d = 0; d < D; d++) { float df = qkv[tid * D + d] - m; vv += df * df; }
        vv *= (1.f / D);
        stat[tid * 2] = m;
        stat[tid * 2 + 1] = rsqrtf(vv + EPS);
    }
    __syncthreads();
    const float* L1W = ln1w + layer * D;
    const float* L1B = ln1b + layer * D;
    for (int i = tid; i < S * D; i += nt) {
        int s = i >> 6, d = i & 63;
        g_x1[i] = (qkv[i] - stat[s * 2]) * stat[s * 2 + 1] * L1W[d] + L1B[d];
        g_y[i] = f2b[layer * D + d];  // seed FFN output with its bias
    }
}

// ---------------------------------------------------------------------------
// Fused FFN: 128 blocks x 128 threads. Block b owns FF units [16b, 16b+16).
// Phase 1: h = relu(x1 @ W1^T + b1) (8 lanes/unit, shfl-reduced, smem).
// Phase 2: partial y contributions atomically added into bias-seeded g_y.
// ---------------------------------------------------------------------------
template <int S>
__global__ void ffn_kernel(const float* __restrict__ f1w,
                           const float* __restrict__ f1b,
                           const float* __restrict__ f2w, int layer) {
    __shared__ __align__(16) float xs[S * D];
    __shared__ __align__(16) float hsm[S * 16];
    int tid = threadIdx.x;
    for (int i = tid; i < S * D; i += 128) xs[i] = g_x1[i];
    __syncthreads();

    int g = tid >> 3, l = tid & 7;
    int f = blockIdx.x * 16 + g;
    const float4* w1r = (const float4*)(f1w + (size_t)layer * FF * D + (size_t)f * D);
    float4 wa = w1r[l * 2], wb = w1r[l * 2 + 1];
    const float4* xs4 = (const float4*)xs;
    float acc[S];
#pragma unroll
    for (int s = 0; s < S; s++) {
        acc[s] = dot4(wa, xs4[s * 16 + l * 2]) + dot4(wb, xs4[s * 16 + l * 2 + 1]);
    }
#pragma unroll
    for (int s = 0; s < S; s++) {
        float v = acc[s];
        v += __shfl_xor_sync(0xffffffffu, v, 4);
        v += __shfl_xor_sync(0xffffffffu, v, 2);
        v += __shfl_xor_sync(0xffffffffu, v, 1);
        acc[s] = v;
    }
    if (l == 0) {
        float b = f1b[layer * FF + f];
#pragma unroll
        for (int s = 0; s < S; s++) hsm[s * 16 + g] = fmaxf(acc[s] + b, 0.f);
    }
    __syncthreads();

    int d = tid >> 1, half = tid & 1;
    const float4* w2r = (const float4*)(f2w + (size_t)layer * D * FF + (size_t)d * FF
                                        + blockIdx.x * 16);
    float4 va = w2r[half * 2], vb = w2r[half * 2 + 1];
    const float4* h4 = (const float4*)hsm;
#pragma unroll
    for (int s = 0; s < S; s++) {
        float r = dot4(va, h4[s * 4 + half * 2]) + dot4(vb, h4[s * 4 + half * 2 + 1]);
        r += __shfl_xor_sync(0xffffffffu, r, 1);
        if (half == 0) atomicAdd(&g_y[s * 64 + d], r);
    }
}

// ---------------------------------------------------------------------------
// Logits + argmax. t==0: read fp32 emb (exact logits), write fp16 copy.
// t>0: scan fp16 copy (half the HBM traffic). 8-lane groups, 2 rows per
// group per iter for MLP. VV % 64 == 0, so no bounds guards needed.
// ---------------------------------------------------------------------------
__global__ void logits_kernel(const float* __restrict__ emb,
                              const float* __restrict__ ln2w,
                              const float* __restrict__ ln2b,
                              float* __restrict__ out, int t, int S) {
    __shared__ float xr[D];
    __shared__ __align__(16) float4 xs4[D / 4];
    __shared__ float stat2[2];
    int tid = threadIdx.x;
    if (tid < D) xr[tid] = g_x1[(S - 1) * D + tid] + g_y[(S - 1) * D + tid];
    __syncthreads();
    if (tid == 0) {
        float m = 0.f;
        for (int d = 0; d < D; d++) m += xr[d];
        m *= (1.f / D);
        float vv = 0.f;
        for (int d = 0; d < D; d++) { float df = xr[d] - m; vv += df * df; }
        vv *= (1.f / D);
        stat2[0] = m;
        stat2[1] = rsqrtf(vv + EPS);
    }
    __syncthreads();
    if (tid < D) {
        float val = (xr[tid] - stat2[0]) * stat2[1] * ln2w[D + tid] + ln2b[D + tid];
        ((float*)xs4)[tid] = val;
    }
    __syncthreads();

    int lane = tid & 31, wid = tid >> 5;
    int grp = lane >> 3, l8 = lane & 7;
    float4 xa = xs4[2 * l8], xb = xs4[2 * l8 + 1];  // x dims [8*l8, 8*l8+8)
    unsigned long long best = 0ull;
    float* orow = out + (size_t)t * VV;

    if (t == 0) {
        for (int base = blockIdx.x * 64; base < VV; base += gridDim.x * 64) {
            int v0 = base + wid * 8 + grp * 2;
#pragma unroll
            for (int r = 0; r < 2; r++) {
                int v = v0 + r;
                const float4* p = (const float4*)(emb + (size_t)v * D);
                float4 a = p[2 * l8], b2 = p[2 * l8 + 1];
                g_embh4[(size_t)v * 8 + l8] = pack8(a, b2);
                float dot = dot4(a, xa) + dot4(b2, xb);
                dot += __shfl_xor_sync(0xffffffffu, dot, 1);
                dot += __shfl_xor_sync(0xffffffffu, dot, 2);
                dot += __shfl_xor_sync(0xffffffffu, dot, 4);
                if (l8 == 0) {
                    orow[v] = dot;
                    unsigned long long key =
                        ((unsigned long long)fkey(dot) << 32) | (0xFFFFFFFFu - (unsigned)v);
                    if (key > best) best = key;
                }
            }
        }
    } else {
        for (int base = blockIdx.x * 64; base < VV; base += gridDim.x * 64) {
            int v0 = base + wid * 8 + grp * 2;
            uint4 q0 = g_embh4[(size_t)v0 * 8 + l8];
            uint4 q1 = g_embh4[(size_t)(v0 + 1) * 8 + l8];
#pragma unroll
            for (int r = 0; r < 2; r++) {
                float dot = dot8h(r ? q1 : q0, xa, xb);
                dot += __shfl_xor_sync(0xffffffffu, dot, 1);
                dot += __shfl_xor_sync(0xffffffffu, dot, 2);
                dot += __shfl_xor_sync(0xffffffffu, dot, 4);
                if (l8 == 0) {
                    int v = v0 + r;
                    orow[v] = dot;
                    unsigned long long key =
                        ((unsigned long long)fkey(dot) << 32) | (0xFFFFFFFFu - (unsigned)v);
                    if (key > best) best = key;
                }
            }
        }
    }

    __shared__ unsigned long long bs[256];
    bs[tid] = best;
    __syncthreads();
    for (int o2 = 128; o2; o2 >>= 1) {
        if (tid < o2) { if (bs[tid + o2] > bs[tid]) bs[tid] = bs[tid + o2]; }
        __syncthreads();
    }
    if (tid == 0) atomicMax(&g_amax[t], bs[0]);
}

__global__ void fin_kernel(float* out, int out_size) {
    if (threadIdx.x == 0) g_gen[STEPS - 1] = dec_idx(g_amax[STEPS - 1]);
    __syncthreads();
    if (out_size >= STEPS * VV + STEPS && threadIdx.x < STEPS)
        out[(size_t)STEPS * VV + threadIdx.x] = (float)g_gen[threadIdx.x];
}

// ---------------------------------------------------------------------------
static void run_ffn(const float* w1, const float* b1, const float* w2,
                    int layer, int S) {
    switch (S) {
        case 1: ffn_kernel<1><<<128, 128>>>(w1, b1, w2, layer); break;
        case 2: ffn_kernel<2><<<128, 128>>>(w1, b1, w2, layer); break;
        case 3: ffn_kernel<3><<<128, 128>>>(w1, b1, w2, layer); break;
        case 4: ffn_kernel<4><<<128, 128>>>(w1, b1, w2, layer); break;
        case 5: ffn_kernel<5><<<128, 128>>>(w1, b1, w2, layer); break;
        case 6: ffn_kernel<6><<<128, 128>>>(w1, b1, w2, layer); break;
        case 7: ffn_kernel<7><<<128, 128>>>(w1, b1, w2, layer); break;
        case 8: ffn_kernel<8><<<128, 128>>>(w1, b1, w2, layer); break;
        case 9: ffn_kernel<9><<<128, 128>>>(w1, b1, w2, layer); break;
        case 10: ffn_kernel<10><<<128, 128>>>(w1, b1, w2, layer); break;
    }
}

extern "C" void kernel_launch(void* const* d_in, const int* in_sizes, int n_in,
                              void* d_out, int out_size) {
    const float* ht  = (const float*)d_in[0];
    const float* emb = (const float*)d_in[1];
    const float* pos = (const float*)d_in[2];
    const float* ipw = (const float*)d_in[3];
    const float* ipb = (const float*)d_in[4];
    const float* ow  = (const float*)d_in[5];
    const float* ob  = (const float*)d_in[6];
    const float* l1w = (const float*)d_in[7];
    const float* l1b = (const float*)d_in[8];
    const float* l2w = (const float*)d_in[9];
    const float* l2b = (const float*)d_in[10];
    const float* f1w = (const float*)d_in[11];
    const float* f1b = (const float*)d_in[12];
    const float* f2w = (const float*)d_in[13];
    const float* f2b = (const float*)d_in[14];
    float* out = (float*)d_out;

    for (int t = 0; t < STEPS; t++) {
        int S = t + 1;
        attn_kernel<<<1, 512>>>(ht, emb, pos, ipw, ipb, ow, ob,
                                l1w, l1b, l2w, l2b, f2b, 0, S, t);
        run_ffn(f1w, f1b, f2w, 0, S);
        attn_kernel<<<1, 512>>>(ht, emb, pos, ipw, ipb, ow, ob,
                                l1w, l1b, l2w, l2b, f2b, 1, S, t);
        run_ffn(f1w, f1b, f2w, 1, S);
        logits_kernel<<<1184, 256>>>(emb, l2w, l2b, out, t, S);
    }
    fin_kernel<<<1, 32>>>(out, out_size);
}